// round 14
// baseline (speedup 1.0000x reference)
#include <cuda_runtime.h>
#include <cuda_bf16.h>

// IoUMetricLoss: pred_label fp32 [8,19,512,1024], label int32 [8,512,1024]
// out: scalar fp32 = 1 - nanmean(IoU per class), all-NaN -> 0.5
//
// R14: split kernels. A (unchanged, 6.5 TB/s proven): streaming argmax ->
// packed uint8 indices. B: R13's 296x1024 shape kept (occ 92%), but the
// global CM epilogue — whose 296-contributor-per-address serialized tail
// (~4.5us) was fully exposed by the persistent grid — now scatters into
// 8 CM replicas (block & 7): 37 contributors/address, tail ~0.6us.

#define NUM_CLASSES 19
#define CM_BINS (NUM_CLASSES * NUM_CLASSES)   // 361
#define CM_REPL 8
#define HW_SHIFT 19                  // 512*1024 = 2^19
#define HW (1 << HW_SHIFT)
#define TOTAL_PIX (8 * HW)           // 4194304
#define VEC_GROUPS (TOTAL_PIX / 4)   // 1048576
#define A_BLOCK 256
#define A_GRID (VEC_GROUPS / A_BLOCK)          // 4096
#define B_BLOCK 1024
#define B_GRID 296                   // 2 CTA/SM
#define B_WARPS (B_BLOCK / 32)       // 32

// Scratch + accumulators (no cudaMalloc allowed). g_idx: 4 packed uint8
// argmax indices per vec-group. g_cm: 8 replicas, statically zero; B's
// finalizer re-zeros them so every graph replay sees clean state.
__device__ unsigned int g_idx[VEC_GROUPS];     // 4 MB scratch
__device__ unsigned int g_cm[CM_REPL][CM_BINS];
__device__ unsigned int g_done;

__device__ __forceinline__ void amax_step(float v, float& bv, int& bi, int c) {
    float m = fmaxf(bv, v);
    bi = (v > bv) ? c : bi;
    bv = m;
}

// ---------- Kernel A: pure streaming argmax (R10-proven, 6.5 TB/s) ----------
__global__ void __launch_bounds__(A_BLOCK)
iou_argmax_kernel(const float* __restrict__ pred) {
    const unsigned t  = blockIdx.x * A_BLOCK + threadIdx.x;  // vec-group id
    const unsigned P  = t << 2;
    const unsigned b  = P >> HW_SHIFT;
    const unsigned hw = P & (HW - 1);

    const float* base = pred + ((size_t)b * NUM_CLASSES << HW_SHIFT) + hw;

    float4 bv = __ldcs((const float4*)base);
    int i0 = 0, i1 = 0, i2 = 0, i3 = 0;
    #pragma unroll
    for (int c = 1; c < NUM_CLASSES; c++) {
        float4 v = __ldcs((const float4*)(base + ((size_t)c << HW_SHIFT)));
        amax_step(v.x, bv.x, i0, c);
        amax_step(v.y, bv.y, i1, c);
        amax_step(v.z, bv.z, i2, c);
        amax_step(v.w, bv.w, i3, c);
    }
    // default-cached store: B reads this right after -> mostly L2-hot
    g_idx[t] = (unsigned)i0 | ((unsigned)i1 << 8) |
               ((unsigned)i2 << 16) | ((unsigned)i3 << 24);
}

// ---------- Kernel B: fat-block histogram + replicated-CM finalize ----------
__global__ void __launch_bounds__(B_BLOCK)
iou_hist_kernel(const int* __restrict__ label, float* __restrict__ out) {
    __shared__ unsigned int s_cm[B_WARPS][CM_BINS];   // 46 KB
    __shared__ int          s_is_last;
    __shared__ float        s_loss;

    const int tid  = threadIdx.x;
    const int warp = tid >> 5;
    const int lane = tid & 31;

    #pragma unroll
    for (int i = lane; i < CM_BINS; i += 32)
        s_cm[warp][i] = 0u;
    __syncwarp();

    // grid-stride over vec-groups: all loads fully coalesced per iteration
    const unsigned stride = B_GRID * B_BLOCK;          // 303104
    for (unsigned t = blockIdx.x * B_BLOCK + tid; t < VEC_GROUPS; t += stride) {
        unsigned pk = g_idx[t];                             // 4B/lane
        int4 lv = __ldcs((const int4*)(label + ((size_t)t << 2)));  // 16B/lane

        int p0 = pk & 0xFF, p1 = (pk >> 8) & 0xFF;
        int p2 = (pk >> 16) & 0xFF, p3 = (pk >> 24) & 0xFF;
        if (lv.x >= 0) atomicAdd(&s_cm[warp][lv.x * NUM_CLASSES + p0], 1u);
        if (lv.y >= 0) atomicAdd(&s_cm[warp][lv.y * NUM_CLASSES + p1], 1u);
        if (lv.z >= 0) atomicAdd(&s_cm[warp][lv.z * NUM_CLASSES + p2], 1u);
        if (lv.w >= 0) atomicAdd(&s_cm[warp][lv.w * NUM_CLASSES + p3], 1u);
    }
    __syncthreads();

    // block reduce -> this block's CM replica: 37 contributors per address
    unsigned int* cm_slot = g_cm[blockIdx.x & (CM_REPL - 1)];
    for (int bin = tid; bin < CM_BINS; bin += B_BLOCK) {
        unsigned s = 0u;
        #pragma unroll
        for (int w = 0; w < B_WARPS; w++) s += s_cm[w][bin];
        if (s) atomicAdd(&cm_slot[bin], s);
    }
    __syncthreads();

    if (tid == 0) {
        __threadfence();
        unsigned prev = atomicAdd(&g_done, 1u);
        s_is_last = (prev == gridDim.x - 1);
    }
    __syncthreads();
    if (!s_is_last) return;

    if (tid < 32) {
        const int c = tid;
        float iou_sum = 0.0f;
        int   valid   = 0;
        if (c < NUM_CLASSES) {
            unsigned long long lab = 0, pr = 0, inter = 0;
            #pragma unroll
            for (int r = 0; r < CM_REPL; r++) {
                #pragma unroll
                for (int k = 0; k < NUM_CLASSES; k++) {
                    lab += g_cm[r][c * NUM_CLASSES + k];   // row: area_label
                    pr  += g_cm[r][k * NUM_CLASSES + c];   // col: area_pred
                }
                inter += g_cm[r][c * NUM_CLASSES + c];
            }
            unsigned long long uni = lab + pr - inter;
            if (uni > 0ULL) {
                iou_sum = (float)inter / (float)uni;
                valid   = 1;
            }
            // uni == 0 -> 0/0 = NaN in reference, excluded by nanmean
        }
        #pragma unroll
        for (int o = 16; o > 0; o >>= 1) {
            iou_sum += __shfl_down_sync(0xFFFFFFFFu, iou_sum, o);
            valid   += __shfl_down_sync(0xFFFFFFFFu, valid, o);
        }
        if (c == 0)
            s_loss = (valid > 0) ? (1.0f - iou_sum / (float)valid) : 0.5f;
    }
    __syncthreads();
    // reset global state for the next graph replay, then emit
    for (int i = tid; i < CM_REPL * CM_BINS; i += B_BLOCK)
        ((unsigned int*)g_cm)[i] = 0u;
    if (tid == 0) {
        g_done = 0u;
        *out = s_loss;
    }
}

extern "C" void kernel_launch(void* const* d_in, const int* in_sizes, int n_in,
                              void* d_out, int out_size) {
    // pred = 79,691,776 elems; label = 4,194,304 (resolve by size).
    const float* pred;
    const int*   label;
    if (in_sizes[0] >= in_sizes[1]) {
        pred  = (const float*)d_in[0];
        label = (const int*)d_in[1];
    } else {
        pred  = (const float*)d_in[1];
        label = (const int*)d_in[0];
    }
    float* out = (float*)d_out;

    iou_argmax_kernel<<<A_GRID, A_BLOCK>>>(pred);
    iou_hist_kernel<<<B_GRID, B_BLOCK>>>(label, out);
}

// round 15
// speedup vs baseline: 1.1102x; 1.1102x over previous
#include <cuda_runtime.h>
#include <cuda_bf16.h>

// IoUMetricLoss: pred_label fp32 [8,19,512,1024], label int32 [8,512,1024]
// out: scalar fp32 = 1 - nanmean(IoU per class), all-NaN -> 0.5
//
// R15: 3 kernels, graph-ordered. A (unchanged, 6.5 TB/s): streaming
// argmax -> packed uint8 indices. B: 296x1024 histogram; epilogue is pure
// RED (atomicAdd, result unused -> 0.854 cyc/op) — the serialized
// atomic-with-return g_done counter (~5us exposed tail in R13, ~44us in
// R11) is DELETED; kernel ordering provides the dependency. C: tiny
// finalize (1 block): loss + state reset for graph replay.

#define NUM_CLASSES 19
#define CM_BINS (NUM_CLASSES * NUM_CLASSES)   // 361
#define HW_SHIFT 19                  // 512*1024 = 2^19
#define HW (1 << HW_SHIFT)
#define TOTAL_PIX (8 * HW)           // 4194304
#define VEC_GROUPS (TOTAL_PIX / 4)   // 1048576
#define A_BLOCK 256
#define A_GRID (VEC_GROUPS / A_BLOCK)          // 4096
#define B_BLOCK 1024
#define B_GRID 296                   // 2 CTA/SM
#define B_HISTS 8                    // 4 warps share one smem hist

// Scratch + accumulators (no cudaMalloc allowed). g_idx: 4 packed uint8
// argmax indices per vec-group. g_cm statically zero; C re-zeros it after
// reading so every graph replay sees clean state.
__device__ unsigned int g_idx[VEC_GROUPS];     // 4 MB scratch
__device__ unsigned int g_cm[CM_BINS];

__device__ __forceinline__ void amax_step(float v, float& bv, int& bi, int c) {
    float m = fmaxf(bv, v);
    bi = (v > bv) ? c : bi;
    bv = m;
}

// ---------- Kernel A: pure streaming argmax (R10-proven, 6.5 TB/s) ----------
__global__ void __launch_bounds__(A_BLOCK)
iou_argmax_kernel(const float* __restrict__ pred) {
    const unsigned t  = blockIdx.x * A_BLOCK + threadIdx.x;  // vec-group id
    const unsigned P  = t << 2;
    const unsigned b  = P >> HW_SHIFT;
    const unsigned hw = P & (HW - 1);

    const float* base = pred + ((size_t)b * NUM_CLASSES << HW_SHIFT) + hw;

    float4 bv = __ldcs((const float4*)base);
    int i0 = 0, i1 = 0, i2 = 0, i3 = 0;
    #pragma unroll
    for (int c = 1; c < NUM_CLASSES; c++) {
        float4 v = __ldcs((const float4*)(base + ((size_t)c << HW_SHIFT)));
        amax_step(v.x, bv.x, i0, c);
        amax_step(v.y, bv.y, i1, c);
        amax_step(v.z, bv.z, i2, c);
        amax_step(v.w, bv.w, i3, c);
    }
    // default-cached store: B reads this right after -> mostly L2-hot
    g_idx[t] = (unsigned)i0 | ((unsigned)i1 << 8) |
               ((unsigned)i2 << 16) | ((unsigned)i3 << 24);
}

// ---------- Kernel B: histogram, RED-only epilogue ----------
__global__ void __launch_bounds__(B_BLOCK)
iou_hist_kernel(const int* __restrict__ label) {
    __shared__ unsigned int s_cm[B_HISTS][CM_BINS];   // 11.5 KB

    const int tid  = threadIdx.x;
    const int hist = tid >> 7;            // 4 warps (128 threads) per hist

    // zero the shared histograms
    for (int i = tid; i < B_HISTS * CM_BINS; i += B_BLOCK)
        ((unsigned int*)s_cm)[i] = 0u;
    __syncthreads();

    // grid-stride over vec-groups: all loads fully coalesced per iteration
    const unsigned stride = B_GRID * B_BLOCK;          // 303104
    for (unsigned t = blockIdx.x * B_BLOCK + tid; t < VEC_GROUPS; t += stride) {
        unsigned pk = g_idx[t];                             // 4B/lane
        int4 lv = __ldcs((const int4*)(label + ((size_t)t << 2)));  // 16B/lane

        int p0 = pk & 0xFF, p1 = (pk >> 8) & 0xFF;
        int p2 = (pk >> 16) & 0xFF, p3 = (pk >> 24) & 0xFF;
        if (lv.x >= 0) atomicAdd(&s_cm[hist][lv.x * NUM_CLASSES + p0], 1u);
        if (lv.y >= 0) atomicAdd(&s_cm[hist][lv.y * NUM_CLASSES + p1], 1u);
        if (lv.z >= 0) atomicAdd(&s_cm[hist][lv.z * NUM_CLASSES + p2], 1u);
        if (lv.w >= 0) atomicAdd(&s_cm[hist][lv.w * NUM_CLASSES + p3], 1u);
    }
    __syncthreads();

    // block reduce -> global CM via RED (result unused -> 0.854 cyc/op)
    for (int bin = tid; bin < CM_BINS; bin += B_BLOCK) {
        unsigned s = 0u;
        #pragma unroll
        for (int h = 0; h < B_HISTS; h++) s += s_cm[h][bin];
        if (s) atomicAdd(&g_cm[bin], s);
    }
    // no done-counter, no fence: kernel boundary orders B before C
}

// ---------- Kernel C: finalize + state reset ----------
__global__ void iou_finalize_kernel(float* __restrict__ out) {
    const int tid = threadIdx.x;     // 64 threads
    __shared__ float s_loss;

    if (tid < 32) {
        const int c = tid;
        float iou_sum = 0.0f;
        int   valid   = 0;
        if (c < NUM_CLASSES) {
            unsigned long long lab = 0, pr = 0;
            #pragma unroll
            for (int k = 0; k < NUM_CLASSES; k++) {
                lab += g_cm[c * NUM_CLASSES + k];   // row sum: area_label
                pr  += g_cm[k * NUM_CLASSES + c];   // col sum: area_pred
            }
            unsigned long long inter = g_cm[c * NUM_CLASSES + c];
            unsigned long long uni   = lab + pr - inter;
            if (uni > 0ULL) {
                iou_sum = (float)inter / (float)uni;
                valid   = 1;
            }
            // uni == 0 -> 0/0 = NaN in reference, excluded by nanmean
        }
        #pragma unroll
        for (int o = 16; o > 0; o >>= 1) {
            iou_sum += __shfl_down_sync(0xFFFFFFFFu, iou_sum, o);
            valid   += __shfl_down_sync(0xFFFFFFFFu, valid, o);
        }
        if (c == 0)
            s_loss = (valid > 0) ? (1.0f - iou_sum / (float)valid) : 0.5f;
    }
    __syncthreads();
    // reset global CM for the next graph replay, then emit
    for (int i = tid; i < CM_BINS; i += blockDim.x)
        g_cm[i] = 0u;
    if (tid == 0)
        *out = s_loss;
}

extern "C" void kernel_launch(void* const* d_in, const int* in_sizes, int n_in,
                              void* d_out, int out_size) {
    // pred = 79,691,776 elems; label = 4,194,304 (resolve by size).
    const float* pred;
    const int*   label;
    if (in_sizes[0] >= in_sizes[1]) {
        pred  = (const float*)d_in[0];
        label = (const int*)d_in[1];
    } else {
        pred  = (const float*)d_in[1];
        label = (const int*)d_in[0];
    }
    float* out = (float*)d_out;

    iou_argmax_kernel<<<A_GRID, A_BLOCK>>>(pred);
    iou_hist_kernel<<<B_GRID, B_BLOCK>>>(label);
    iou_finalize_kernel<<<1, 64>>>(out);
}